// round 1
// baseline (speedup 1.0000x reference)
#include <cuda_runtime.h>
#include <cuda_bf16.h>

// P(|00> on wires 0,1) depends ONLY on the query register:
//  - query/key circuits act on disjoint registers (product state)
//  - CRY is controlled on query bits (doesn't change query amplitudes);
//    conditioned on query bitstring a, the key register evolves unitarily
//  - CRZ is diagonal (phases only)
//  => P = sum_{a: a0=a1=0} |psi_q(a)|^2, exactly.
// Per-sample: 4-qubit (16 complex amps) statevector sim in registers.

__global__ void vqa_kernel(const float* __restrict__ query,
                           const float* __restrict__ W_q_y,   // (2,4)
                           const float* __restrict__ W_q_z,   // (2,4)
                           float* __restrict__ out, int B) {
    int b = blockIdx.x * blockDim.x + threadIdx.x;
    if (b >= B) return;

    const float PI = 3.14159265358979323846f;
    float q[4];
#pragma unroll
    for (int i = 0; i < 4; i++)
        q[i] = tanhf(query[(long long)b * 64 + i]) * PI;

    // state: wire0 = most significant bit of index a
    float sr[16], si[16];
#pragma unroll
    for (int a = 0; a < 16; a++) { sr[a] = 0.0f; si[a] = 0.0f; }
    sr[0] = 1.0f;

#pragma unroll
    for (int layer = 0; layer < 2; layer++) {
#pragma unroll
        for (int w = 0; w < 4; w++) {
            const int mask = 8 >> w;
            // fused RY(q[w]*pi) * RY(W_q_y) = RY(q[w]*pi + W_q_y)
            float th = q[w] + W_q_y[layer * 4 + w];
            float s, c;
            sincosf(0.5f * th, &s, &c);
#pragma unroll
            for (int a = 0; a < 16; a++) {
                if (a & mask) continue;
                const int a1 = a | mask;
                float r0 = sr[a], i0 = si[a], r1 = sr[a1], i1 = si[a1];
                sr[a]  = c * r0 - s * r1;  si[a]  = c * i0 - s * i1;
                sr[a1] = s * r0 + c * r1;  si[a1] = s * i0 + c * i1;
            }
            // RZ(W_q_z): diag(e^{-iz/2}, e^{+iz/2}) on wire w
            float z = W_q_z[layer * 4 + w];
            float sz, cz;
            sincosf(0.5f * z, &sz, &cz);
#pragma unroll
            for (int a = 0; a < 16; a++) {
                float sgn = (a & mask) ? sz : -sz;   // imag part of phase
                float r = sr[a], im = si[a];
                sr[a] = cz * r - sgn * im;
                si[a] = cz * im + sgn * r;
            }
        }
        // CNOT chain: control w -> target w+1 (basis permutation)
#pragma unroll
        for (int w = 0; w < 3; w++) {
            const int cm = 8 >> w, tm = 8 >> (w + 1);
#pragma unroll
            for (int a = 0; a < 16; a++) {
                if ((a & cm) && !(a & tm)) {
                    const int a1 = a | tm;
                    float tr = sr[a], ti = si[a];
                    sr[a] = sr[a1];  si[a] = si[a1];
                    sr[a1] = tr;     si[a1] = ti;
                }
            }
        }
    }

    // P(wire0=0, wire1=0): indices 0..3 (bits 3,2 of a are wires 0,1)
    float p = 0.0f;
#pragma unroll
    for (int a = 0; a < 4; a++)
        p += sr[a] * sr[a] + si[a] * si[a];
    out[b] = p;
}

extern "C" void kernel_launch(void* const* d_in, const int* in_sizes, int n_in,
                              void* d_out, int out_size) {
    const float* query = (const float*)d_in[0];
    // d_in[1] = key      (unused — provably irrelevant to the output)
    const float* W_q_y = (const float*)d_in[2];
    const float* W_q_z = (const float*)d_in[3];
    // d_in[4..6] = W_k_y, W_k_z, W_int (unused — provably irrelevant)
    float* out = (float*)d_out;
    int B = out_size;

    const int threads = 128;
    const int blocks = (B + threads - 1) / threads;
    vqa_kernel<<<blocks, threads>>>(query, W_q_y, W_q_z, out, B);
}

// round 2
// speedup vs baseline: 1.0348x; 1.0348x over previous
#include <cuda_runtime.h>
#include <cuda_bf16.h>

// Exact reductions (all algebraic, not approximations):
//  - key register / W_k / W_int never affect P(wires 0,1 = |00>)  [unitarity + diagonality]
//  - layer-2 RZs: diagonal, commute to the end -> phases -> dropped
//  - layer-2 CNOT chain: basis permutation; measured condition maps to pre-chain indices {0..3}
//  - layer-2 RYs on wires 2,3: act within subspace {0..3} -> norm-preserving -> dropped
//  - layer 1: product state (tensor product of four 2-vectors), CNOT chain = static index remap
// Remaining: P = sum_{x=0..3} | c0*(c1*L[x]-s1*L[x+4]) - s0*(c1*L[x+8]-s1*L[x+12]) |^2
// where L[x] = v0[x3] v1[x2^x3] v2[x1^x2] v3[x0^x1],  v_w = RZ(z_w)RY(th_w)|0>.

__global__ void vqa_kernel(const float4* __restrict__ query4,
                           const float* __restrict__ Wqy,   // (2,4)
                           const float* __restrict__ Wqz,   // (2,4)
                           float* __restrict__ out, int B) {
    int b = blockIdx.x * blockDim.x + threadIdx.x;
    if (b >= B) return;

    const float PI = 3.14159265358979323846f;
    float4 qv = query4[(long long)b * 16];   // first 4 of 64 floats per row
    float q[4] = {qv.x, qv.y, qv.z, qv.w};

    float th[4];
#pragma unroll
    for (int i = 0; i < 4; i++) {
        // tanh(x) = 1 - 2/(e^{2x}+1), via MUFU ex2 + fast rcp (~1e-7 err)
        float e = __expf(2.0f * q[i]);
        th[i] = (1.0f - __fdividef(2.0f, e + 1.0f)) * PI;
    }

    // Layer 1: per-wire 2-vectors v_w = RZ(z) RY(theta) |0>
    float vr[4][2], vi[4][2];
#pragma unroll
    for (int w = 0; w < 4; w++) {
        float s, c, sz, cz;
        __sincosf(0.5f * (th[w] + Wqy[w]), &s, &c);
        __sincosf(0.5f * Wqz[w], &sz, &cz);
        vr[w][0] = c * cz;  vi[w][0] = -c * sz;
        vr[w][1] = s * cz;  vi[w][1] =  s * sz;
    }

    // Pairwise tensor products (complex)
    float p01r[2][2], p01i[2][2], p23r[2][2], p23i[2][2];
#pragma unroll
    for (int i = 0; i < 2; i++)
#pragma unroll
        for (int j = 0; j < 2; j++) {
            p01r[i][j] = vr[0][i] * vr[1][j] - vi[0][i] * vi[1][j];
            p01i[i][j] = vr[0][i] * vi[1][j] + vi[0][i] * vr[1][j];
            p23r[i][j] = vr[2][i] * vr[3][j] - vi[2][i] * vi[3][j];
            p23i[i][j] = vr[2][i] * vi[3][j] + vi[2][i] * vr[3][j];
        }

    // Layer-1 output incl. CNOT chain: L[x] = p01[x3][x2^x3] * p23[x1^x2][x0^x1]
    float Lr[16], Li[16];
#pragma unroll
    for (int x = 0; x < 16; x++) {
        const int x3 = (x >> 3) & 1;
        const int i2 = ((x >> 2) ^ (x >> 3)) & 1;
        const int i1 = ((x >> 1) ^ (x >> 2)) & 1;
        const int i0 = (x ^ (x >> 1)) & 1;
        float ar = p01r[x3][i2], ai = p01i[x3][i2];
        float br = p23r[i1][i0], bi = p23i[i1][i0];
        Lr[x] = ar * br - ai * bi;
        Li[x] = ar * bi + ai * br;
    }

    // Layer 2: only RY on wires 0 and 1 matter
    float s0, c0, s1, c1;
    __sincosf(0.5f * (th[0] + Wqy[4 + 0]), &s0, &c0);
    __sincosf(0.5f * (th[1] + Wqy[4 + 1]), &s1, &c1);

    float p = 0.0f;
#pragma unroll
    for (int x = 0; x < 4; x++) {
        float ar = c1 * Lr[x]     - s1 * Lr[x + 4];
        float ai = c1 * Li[x]     - s1 * Li[x + 4];
        float br = c1 * Lr[x + 8] - s1 * Lr[x + 12];
        float bi = c1 * Li[x + 8] - s1 * Li[x + 12];
        float fr = c0 * ar - s0 * br;
        float fi = c0 * ai - s0 * bi;
        p = fmaf(fr, fr, fmaf(fi, fi, p));
    }
    out[b] = p;
}

extern "C" void kernel_launch(void* const* d_in, const int* in_sizes, int n_in,
                              void* d_out, int out_size) {
    const float4* query = (const float4*)d_in[0];
    const float* W_q_y = (const float*)d_in[2];
    const float* W_q_z = (const float*)d_in[3];
    float* out = (float*)d_out;
    int B = out_size;

    const int threads = 128;
    const int blocks = (B + threads - 1) / threads;
    vqa_kernel<<<blocks, threads>>>(query, W_q_y, W_q_z, out, B);
}